// round 6
// baseline (speedup 1.0000x reference)
#include <cuda_runtime.h>
#include <math.h>

#define N_PTS 16384
#define MAXNB 64
#define NCLOUD 8
#define GDIM 16
#define NCELLS (NCLOUD*GDIM*GDIM*GDIM)   // 32768
#define CAP 32
#define FULL 0xffffffffu

#define NBLOCKS 592                      // 148 SMs * 4 resident CTAs (guaranteed wave-1)
#define NTHREADS 256
#define TOTTHR (NBLOCKS*NTHREADS)        // 151552
#define TOTWARP (NBLOCKS*8)              // 4736

// ---- scratch (device globals; no allocation allowed) ----
__device__ int    d_count[NCELLS];
__device__ int    d_cell[NCELLS*CAP];
__device__ float4 d_pos4[N_PTS];                 // x,y,z,sq
__device__ int    d_nbr[N_PTS*MAXNB];
__device__ int    d_cnt[N_PTS];
__device__ float  d_ua[N_PTS*8],  d_va[N_PTS*8];
__device__ float  d_ub[N_PTS*16], d_vb[N_PTS*16];
__device__ float  d_uc[N_PTS*32], d_vc[N_PTS*32];

// software grid barrier (all NBLOCKS blocks are resident by construction)
__device__ volatile int d_bar_count;
__device__ volatile int d_bar_gen;

__device__ __forceinline__ void grid_sync() {
    __syncthreads();
    if (threadIdx.x == 0) {
        __threadfence();                          // publish this block's phase data
        int gen = d_bar_gen;
        int t = atomicAdd((int*)&d_bar_count, 1);
        if (t == NBLOCKS - 1) {
            d_bar_count = 0;
            __threadfence();
            d_bar_gen = gen + 1;                  // release
        } else {
            while (d_bar_gen == gen) { }          // spin (volatile)
            __threadfence();                      // acquire
        }
    }
    __syncthreads();
}

__global__ void __launch_bounds__(NTHREADS, 4)
fused_kernel(const float* __restrict__ pos, const int* __restrict__ batch,
             const float* __restrict__ W1a, const float* __restrict__ b1a,
             const float* __restrict__ W2a, const float* __restrict__ b2a,
             const float* __restrict__ W1b, const float* __restrict__ b1b,
             const float* __restrict__ W2b, const float* __restrict__ b2b,
             const float* __restrict__ W1c, const float* __restrict__ b1c,
             const float* __restrict__ W2c, const float* __restrict__ b2c,
             float* __restrict__ out, float* __restrict__ feat_out, int aux) {
    const int tid  = blockIdx.x * NTHREADS + threadIdx.x;
    const int warp = tid >> 5;
    const int lane = threadIdx.x & 31;

    // ---- phase 0: zero grid counts ----
    for (int t = tid; t < NCELLS; t += TOTTHR) d_count[t] = 0;
    grid_sync();

    // ---- phase 1: pack pos4, grid insert, aux copies ----
    for (int i = tid; i < N_PTS; i += TOTTHR) {
        float px = pos[3*i+0], py = pos[3*i+1], pz = pos[3*i+2];
        float sq = (px*px + py*py) + pz*pz;        // match jnp.sum(pos*pos) order
        d_pos4[i] = make_float4(px, py, pz, sq);
        int c  = batch[i];
        int cx = min(GDIM-1, (int)(px * GDIM));
        int cy = min(GDIM-1, (int)(py * GDIM));
        int cz = min(GDIM-1, (int)(pz * GDIM));
        int cell = ((c * GDIM + cz) * GDIM + cy) * GDIM + cx;
        int slot = atomicAdd(&d_count[cell], 1);
        if (slot < CAP) d_cell[cell*CAP + slot] = i;
        if (aux) {
            out[3*i+0] = px; out[3*i+1] = py; out[3*i+2] = pz;
            out[N_PTS*3 + N_PTS*32 + i] = (float)c;
        }
    }
    grid_sync();

    // ---- phase 2: 27-cell stencil radius scan + layer-a u/v prep ----
    for (int i = tid; i < N_PTS; i += TOTTHR) {
        float4 p = d_pos4[i];
        const float r2 = (1.0f/16.0f) * (1.0f/16.0f);
        int c  = batch[i];
        int cx = min(GDIM-1, (int)(p.x * GDIM));
        int cy = min(GDIM-1, (int)(p.y * GDIM));
        int cz = min(GDIM-1, (int)(p.z * GDIM));
        int cnt = 0;
        for (int dz = max(cz-1,0); dz <= min(cz+1,GDIM-1); dz++)
        for (int dy = max(cy-1,0); dy <= min(cy+1,GDIM-1); dy++)
        for (int dx = max(cx-1,0); dx <= min(cx+1,GDIM-1); dx++) {
            int cell = ((c * GDIM + dz) * GDIM + dy) * GDIM + dx;
            int m = min(d_count[cell], CAP);
            for (int t = 0; t < m; t++) {
                int j = d_cell[cell*CAP + t];
                float4 q = d_pos4[j];
                float dot = (p.x*q.x + p.y*q.y) + p.z*q.z;
                float d2  = fmaxf(p.w + q.w - 2.0f*dot, 0.0f);  // exact reference formula
                if (d2 <= r2 && cnt < MAXNB) d_nbr[i*MAXNB + cnt++] = j;
            }
        }
        d_cnt[i] = cnt;
        #pragma unroll
        for (int m = 0; m < 8; m++) {
            float tf = p.x*W1a[0*8+m] + p.y*W1a[1*8+m] + p.z*W1a[2*8+m];
            float tp = p.x*W1a[3*8+m] + p.y*W1a[4*8+m] + p.z*W1a[5*8+m];
            d_ua[i*8+m] = b1a[m] + tf + tp;
            d_va[i*8+m] = tp;
        }
    }
    grid_sync();

    // ---- phase 3: conv a (CMID=8, 4 replicas) + layer-b u/v prep ----
    for (int i = warp; i < N_PTS; i += TOTWARP) {
        const int m = lane & 7, rep = lane >> 3;
        float v = d_va[i*8+m];
        int cnt = d_cnt[i];
        float best = -INFINITY;
        for (int k = rep; k < cnt; k += 4) {
            int j = d_nbr[i*MAXNB + k];
            best = fmaxf(best, fmaxf(d_ua[j*8+m] - v, 0.0f));
        }
        best = fmaxf(best, __shfl_xor_sync(FULL, best, 8));
        best = fmaxf(best, __shfl_xor_sync(FULL, best, 16));
        if (!isfinite(best)) best = 0.0f;
        float acc = b2a[m];
        #pragma unroll
        for (int mm = 0; mm < 8; mm++)
            acc += __shfl_sync(FULL, best, mm) * W2a[mm*8+m];
        acc = (acc > 0.0f) ? acc : expm1f(acc);    // celu; lanes 0..7 hold out
        float4 p = d_pos4[i];
        int mb = lane & 15;
        float tp = p.x*W1b[8*16+mb] + p.y*W1b[9*16+mb] + p.z*W1b[10*16+mb];
        float u = b1b[mb] + tp;
        #pragma unroll
        for (int f = 0; f < 8; f++)
            u += __shfl_sync(FULL, acc, f) * W1b[f*16+mb];
        if (lane < 16) { d_ub[i*16+mb] = u; d_vb[i*16+mb] = tp; }
    }
    grid_sync();

    // ---- phase 4: conv b (CMID=16, 2 replicas) + layer-c u/v prep ----
    for (int i = warp; i < N_PTS; i += TOTWARP) {
        const int m = lane & 15, rep = lane >> 4;
        float v = d_vb[i*16+m];
        int cnt = d_cnt[i];
        float best = -INFINITY;
        for (int k = rep; k < cnt; k += 2) {
            int j = d_nbr[i*MAXNB + k];
            best = fmaxf(best, fmaxf(d_ub[j*16+m] - v, 0.0f));
        }
        best = fmaxf(best, __shfl_xor_sync(FULL, best, 16));
        if (!isfinite(best)) best = 0.0f;
        float acc = b2b[m];
        #pragma unroll
        for (int mm = 0; mm < 16; mm++)
            acc += __shfl_sync(FULL, best, mm) * W2b[mm*16+m];
        acc = (acc > 0.0f) ? acc : expm1f(acc);    // lanes 0..15 hold out
        float4 p = d_pos4[i];
        float tp = p.x*W1c[16*32+lane] + p.y*W1c[17*32+lane] + p.z*W1c[18*32+lane];
        float u = b1c[lane] + tp;
        #pragma unroll
        for (int f = 0; f < 16; f++)
            u += __shfl_sync(FULL, acc, f) * W1c[f*32+lane];
        d_uc[i*32+lane] = u;
        d_vc[i*32+lane] = tp;
    }
    grid_sync();

    // ---- phase 5: conv c (CMID=32) -> final output ----
    for (int i = warp; i < N_PTS; i += TOTWARP) {
        float v = d_vc[i*32+lane];
        int cnt = d_cnt[i];
        float best = -INFINITY;
        for (int k = 0; k < cnt; k++) {
            int j = d_nbr[i*MAXNB + k];
            best = fmaxf(best, fmaxf(d_uc[j*32+lane] - v, 0.0f));
        }
        if (!isfinite(best)) best = 0.0f;
        float acc = b2c[lane];
        #pragma unroll
        for (int mm = 0; mm < 32; mm++)
            acc += __shfl_sync(FULL, best, mm) * W2c[mm*32+lane];
        acc = (acc > 0.0f) ? acc : expm1f(acc);
        feat_out[i*32+lane] = acc;
    }
}

extern "C" void kernel_launch(void* const* d_in, const int* in_sizes, int n_in,
                              void* d_out, int out_size) {
    const float* pos   = (const float*)d_in[0];
    const int*   batch = (const int*)d_in[2];
    const float* W1a = (const float*)d_in[3];
    const float* b1a = (const float*)d_in[4];
    const float* W2a = (const float*)d_in[5];
    const float* b2a = (const float*)d_in[6];
    const float* W1b = (const float*)d_in[7];
    const float* b1b = (const float*)d_in[8];
    const float* W2b = (const float*)d_in[9];
    const float* b2b = (const float*)d_in[10];
    const float* W1c = (const float*)d_in[11];
    const float* b1c = (const float*)d_in[12];
    const float* W2c = (const float*)d_in[13];
    const float* b2c = (const float*)d_in[14];

    float* out = (float*)d_out;
    const int full_size = N_PTS*3 + N_PTS*32 + N_PTS;   // pos + feat + batch
    const int aux = (out_size >= full_size) ? 1 : 0;
    float* feat_out = out + (aux ? N_PTS*3 : 0);

    fused_kernel<<<NBLOCKS, NTHREADS>>>(pos, batch,
        W1a, b1a, W2a, b2a, W1b, b1b, W2b, b2b, W1c, b1c, W2c, b2c,
        out, feat_out, aux);
}

// round 7
// speedup vs baseline: 1.2917x; 1.2917x over previous
#include <cuda_runtime.h>
#include <math.h>

#define N_PTS 16384
#define MAXNB 64
#define NCLOUD 8
#define GDIM 16
#define NCELLS (NCLOUD*GDIM*GDIM*GDIM)   // 32768
#define CAP 32
#define FULL 0xffffffffu

// ---- scratch (device globals; no allocation allowed) ----
__device__ int    d_count[NCELLS];
__device__ int    d_cell[NCELLS*CAP];
__device__ float4 d_pos4[N_PTS];                 // x,y,z,sq
__device__ int    d_nbr[N_PTS*MAXNB];
__device__ int    d_cnt[N_PTS];
__device__ float  d_ua[N_PTS*8],  d_va[N_PTS*8];
__device__ float  d_ub[N_PTS*16], d_vb[N_PTS*16];
__device__ float  d_uc[N_PTS*32], d_vc[N_PTS*32];

// thread-per-point: pack pos4, insert into grid, copy aux outputs
__global__ void fill_grid(const float* __restrict__ pos, const int* __restrict__ batch,
                          float* __restrict__ out, int aux) {
    int i = blockIdx.x * blockDim.x + threadIdx.x;
    if (i >= N_PTS) return;
    float px = pos[3*i+0], py = pos[3*i+1], pz = pos[3*i+2];
    float sq = (px*px + py*py) + pz*pz;          // match jnp.sum(pos*pos) order
    d_pos4[i] = make_float4(px, py, pz, sq);
    int c  = batch[i];
    int cx = min(GDIM-1, (int)(px * GDIM));
    int cy = min(GDIM-1, (int)(py * GDIM));
    int cz = min(GDIM-1, (int)(pz * GDIM));
    int cell = ((c * GDIM + cz) * GDIM + cy) * GDIM + cx;
    int slot = atomicAdd(&d_count[cell], 1);
    if (slot < CAP) d_cell[cell*CAP + slot] = i;
    if (aux) {
        out[3*i+0] = px; out[3*i+1] = py; out[3*i+2] = pz;
        out[N_PTS*3 + N_PTS*32 + i] = (float)c;
    }
}

// thread-per-point: 27-cell stencil radius scan + layer-a u/v prep
__global__ void build_nbrs(const int* __restrict__ batch,
                           const float* __restrict__ W1a, const float* __restrict__ b1a) {
    int i = blockIdx.x * blockDim.x + threadIdx.x;
    if (i >= N_PTS) return;
    float4 p = d_pos4[i];
    const float r2 = (1.0f/16.0f) * (1.0f/16.0f);
    int c  = batch[i];
    int cx = min(GDIM-1, (int)(p.x * GDIM));
    int cy = min(GDIM-1, (int)(p.y * GDIM));
    int cz = min(GDIM-1, (int)(p.z * GDIM));
    int cnt = 0;
    for (int dz = max(cz-1,0); dz <= min(cz+1,GDIM-1); dz++)
    for (int dy = max(cy-1,0); dy <= min(cy+1,GDIM-1); dy++)
    for (int dx = max(cx-1,0); dx <= min(cx+1,GDIM-1); dx++) {
        int cell = ((c * GDIM + dz) * GDIM + dy) * GDIM + dx;
        int m = min(d_count[cell], CAP);
        for (int t = 0; t < m; t++) {
            int j = d_cell[cell*CAP + t];
            float4 q = d_pos4[j];
            float dot = (p.x*q.x + p.y*q.y) + p.z*q.z;
            float d2  = fmaxf(p.w + q.w - 2.0f*dot, 0.0f);   // exact reference formula
            if (d2 <= r2 && cnt < MAXNB) d_nbr[i*MAXNB + cnt++] = j;
        }
    }
    d_cnt[i] = cnt;
    // prep layer a: u_a = b1 + pos@W1x + pos@W1p ; v_a = pos@W1p  (input x == pos)
    #pragma unroll
    for (int m = 0; m < 8; m++) {
        float tf = p.x*W1a[0*8+m] + p.y*W1a[1*8+m] + p.z*W1a[2*8+m];
        float tp = p.x*W1a[3*8+m] + p.y*W1a[4*8+m] + p.z*W1a[5*8+m];
        d_ua[i*8+m] = b1a[m] + tf + tp;
        d_va[i*8+m] = tp;
    }
}

// layer a conv: 4 points/warp, 8-lane group = 8 channels; + layer-b u/v prep
__global__ void conv_a(const float* __restrict__ W2, const float* __restrict__ b2,
                       const float* __restrict__ W1n, const float* __restrict__ b1n) {
    int lane = threadIdx.x & 31;
    int warp = (blockIdx.x * blockDim.x + threadIdx.x) >> 5;   // 0..4095 exactly
    const int g = lane >> 3, m = lane & 7;
    const int i = warp * 4 + g;
    float v = d_va[i*8+m];
    int cnt = d_cnt[i];
    float best = -INFINITY;
    for (int k = 0; k < cnt; k++) {
        int j = d_nbr[i*MAXNB + k];
        best = fmaxf(best, fmaxf(d_ua[j*8+m] - v, 0.0f));
    }
    if (!isfinite(best)) best = 0.0f;
    float acc = b2[m];
    #pragma unroll
    for (int mm = 0; mm < 8; mm++)
        acc += __shfl_sync(FULL, best, mm, 8) * W2[mm*8+m];
    acc = (acc > 0.0f) ? acc : expm1f(acc);      // celu; lane m of group holds out[m]
    // prep layer b: channels m and m+8
    float4 p = d_pos4[i];
    float tp0 = p.x*W1n[8*16+m]   + p.y*W1n[9*16+m]   + p.z*W1n[10*16+m];
    float tp1 = p.x*W1n[8*16+m+8] + p.y*W1n[9*16+m+8] + p.z*W1n[10*16+m+8];
    float u0 = b1n[m]   + tp0;
    float u1 = b1n[m+8] + tp1;
    #pragma unroll
    for (int f = 0; f < 8; f++) {
        float xf = __shfl_sync(FULL, acc, f, 8);
        u0 += xf * W1n[f*16+m];
        u1 += xf * W1n[f*16+m+8];
    }
    d_ub[i*16+m]   = u0;  d_vb[i*16+m]   = tp0;
    d_ub[i*16+m+8] = u1;  d_vb[i*16+m+8] = tp1;
}

// layer b conv: 2 points/warp, 16-lane group = 16 channels; + layer-c u/v prep
__global__ void conv_b(const float* __restrict__ W2, const float* __restrict__ b2,
                       const float* __restrict__ W1n, const float* __restrict__ b1n) {
    int lane = threadIdx.x & 31;
    int warp = (blockIdx.x * blockDim.x + threadIdx.x) >> 5;   // 0..8191 exactly
    const int g = lane >> 4, m = lane & 15;
    const int i = warp * 2 + g;
    float v = d_vb[i*16+m];
    int cnt = d_cnt[i];
    float best = -INFINITY;
    for (int k = 0; k < cnt; k++) {
        int j = d_nbr[i*MAXNB + k];
        best = fmaxf(best, fmaxf(d_ub[j*16+m] - v, 0.0f));
    }
    if (!isfinite(best)) best = 0.0f;
    float acc = b2[m];
    #pragma unroll
    for (int mm = 0; mm < 16; mm++)
        acc += __shfl_sync(FULL, best, mm, 16) * W2[mm*16+m];
    acc = (acc > 0.0f) ? acc : expm1f(acc);      // lane m of group holds out[m]
    // prep layer c: channels m and m+16
    float4 p = d_pos4[i];
    float tp0 = p.x*W1n[16*32+m]    + p.y*W1n[17*32+m]    + p.z*W1n[18*32+m];
    float tp1 = p.x*W1n[16*32+m+16] + p.y*W1n[17*32+m+16] + p.z*W1n[18*32+m+16];
    float u0 = b1n[m]    + tp0;
    float u1 = b1n[m+16] + tp1;
    #pragma unroll
    for (int f = 0; f < 16; f++) {
        float xf = __shfl_sync(FULL, acc, f, 16);
        u0 += xf * W1n[f*32+m];
        u1 += xf * W1n[f*32+m+16];
    }
    d_uc[i*32+m]    = u0;  d_vc[i*32+m]    = tp0;
    d_uc[i*32+m+16] = u1;  d_vc[i*32+m+16] = tp1;
}

// layer c conv (CMID=32, warp-per-point) -> final output
__global__ void conv_c(const float* __restrict__ W2, const float* __restrict__ b2,
                       float* __restrict__ outp) {
    int warp = (blockIdx.x * blockDim.x + threadIdx.x) >> 5;
    int lane = threadIdx.x & 31;
    const int i = warp;                         // 0..16383 exactly
    float v = d_vc[i*32+lane];
    int cnt = d_cnt[i];
    float best = -INFINITY;
    for (int k = 0; k < cnt; k++) {
        int j = d_nbr[i*MAXNB + k];
        best = fmaxf(best, fmaxf(d_uc[j*32+lane] - v, 0.0f));
    }
    if (!isfinite(best)) best = 0.0f;
    float acc = b2[lane];
    #pragma unroll
    for (int mm = 0; mm < 32; mm++)
        acc += __shfl_sync(FULL, best, mm) * W2[mm*32+lane];
    acc = (acc > 0.0f) ? acc : expm1f(acc);
    outp[i*32+lane] = acc;
}

extern "C" void kernel_launch(void* const* d_in, const int* in_sizes, int n_in,
                              void* d_out, int out_size) {
    const float* pos   = (const float*)d_in[0];
    const int*   batch = (const int*)d_in[2];
    const float* W1a = (const float*)d_in[3];
    const float* b1a = (const float*)d_in[4];
    const float* W2a = (const float*)d_in[5];
    const float* b2a = (const float*)d_in[6];
    const float* W1b = (const float*)d_in[7];
    const float* b1b = (const float*)d_in[8];
    const float* W2b = (const float*)d_in[9];
    const float* b2b = (const float*)d_in[10];
    const float* W1c = (const float*)d_in[11];
    const float* b1c = (const float*)d_in[12];
    const float* W2c = (const float*)d_in[13];
    const float* b2c = (const float*)d_in[14];

    float* out = (float*)d_out;
    const int full_size = N_PTS*3 + N_PTS*32 + N_PTS;   // pos + feat + batch
    const int aux = (out_size >= full_size) ? 1 : 0;
    float* feat_out = out + (aux ? N_PTS*3 : 0);

    // zero grid counts via a memset node (cheaper than a kernel launch)
    void* count_ptr = nullptr;
    cudaGetSymbolAddress(&count_ptr, d_count);
    cudaMemsetAsync(count_ptr, 0, NCELLS * sizeof(int));

    fill_grid <<<(N_PTS + 255)/256, 256>>>(pos, batch, out, aux);
    build_nbrs<<<(N_PTS + 255)/256, 256>>>(batch, W1a, b1a);

    conv_a<<< (N_PTS/4)*32/256, 256>>>(W2a, b2a, W1b, b1b);   // 512 blocks
    conv_b<<< (N_PTS/2)*32/256, 256>>>(W2b, b2b, W1c, b1c);   // 1024 blocks
    conv_c<<<  N_PTS   *32/256, 256>>>(W2c, b2c, feat_out);   // 2048 blocks
}